// round 1
// baseline (speedup 1.0000x reference)
#include <cuda_runtime.h>
#include <math.h>

#define S_LEN  2048
#define B_SZ   4
#define F_DIM  512
#define NHEAD  8
#define NB     32     // B*H
#define HD     64
#define M_ROWS 8192   // S*B
#define FPAD   68

// scratch (static __device__ arrays: no allocation allowed)
__device__ float g_Q[(size_t)NB * S_LEN * HD];
__device__ float g_K[(size_t)NB * S_LEN * HD];
__device__ float g_V[(size_t)NB * S_LEN * HD];
__device__ float g_Y[(size_t)M_ROWS * F_DIM];
__device__ float g_cos[S_LEN * (HD / 2)];
__device__ float g_sin[S_LEN * (HD / 2)];

// ---------------------------------------------------------------------------
// RoPE table: double-precision angle generation (s up to 2047 rad)
// ---------------------------------------------------------------------------
__global__ void rope_table_kernel() {
    int idx = blockIdx.x * blockDim.x + threadIdx.x;
    if (idx >= S_LEN * (HD / 2)) return;
    int s = idx >> 5;
    int j = idx & 31;
    double theta = pow(10000.0, -(double)j / 32.0);
    double ang = (double)s * theta;
    g_cos[idx] = (float)cos(ang);
    g_sin[idx] = (float)sin(ang);
}

// ---------------------------------------------------------------------------
// Projection GEMM: C[m,n] = relu(sum_k A[m,k]*W[n,k] + bias[n])
// MODE 0: flat row-major out (output projection)
// MODE 1: head layout (B*H, S, D), no rope (V)
// MODE 2: head layout + interleaved RoPE (Q, K)
// BM=BN=64, BK=16, 256 threads, 4x4 per thread
// ---------------------------------------------------------------------------
template <int MODE>
__global__ __launch_bounds__(256) void proj_kernel(
    const float* __restrict__ A, const float* __restrict__ W,
    const float* __restrict__ bias, float* __restrict__ out)
{
    __shared__ float AsT[16][FPAD];
    __shared__ float WsT[16][FPAD];

    int tid = threadIdx.x;
    int tx = tid & 15, ty = tid >> 4;
    int m0 = blockIdx.y * 64, n0 = blockIdx.x * 64;

    float acc[4][4];
#pragma unroll
    for (int i = 0; i < 4; i++)
#pragma unroll
        for (int j = 0; j < 4; j++) acc[i][j] = 0.f;

    int lm = tid >> 2;
    int lk = (tid & 3) * 4;
    const float* Ap = A + (size_t)(m0 + lm) * F_DIM + lk;
    const float* Wp = W + (size_t)(n0 + lm) * F_DIM + lk;

    for (int k0 = 0; k0 < F_DIM; k0 += 16) {
        float4 av = *(const float4*)(Ap + k0);
        float4 wv = *(const float4*)(Wp + k0);
        AsT[lk + 0][lm] = av.x; AsT[lk + 1][lm] = av.y;
        AsT[lk + 2][lm] = av.z; AsT[lk + 3][lm] = av.w;
        WsT[lk + 0][lm] = wv.x; WsT[lk + 1][lm] = wv.y;
        WsT[lk + 2][lm] = wv.z; WsT[lk + 3][lm] = wv.w;
        __syncthreads();
#pragma unroll
        for (int k = 0; k < 16; k++) {
            float4 a = *(const float4*)&AsT[k][ty * 4];
            float4 b = *(const float4*)&WsT[k][tx * 4];
            float af[4] = {a.x, a.y, a.z, a.w};
            float bf[4] = {b.x, b.y, b.z, b.w};
#pragma unroll
            for (int i = 0; i < 4; i++)
#pragma unroll
                for (int j = 0; j < 4; j++)
                    acc[i][j] = fmaf(af[i], bf[j], acc[i][j]);
        }
        __syncthreads();
    }

    int nbase = n0 + tx * 4;
#pragma unroll
    for (int i = 0; i < 4; i++) {
        int m = m0 + ty * 4 + i;
        int s = m >> 2;       // row = s*B + b
        int b = m & 3;
        float vv[4];
#pragma unroll
        for (int j = 0; j < 4; j++)
            vv[j] = fmaxf(acc[i][j] + bias[nbase + j], 0.f);

        if (MODE == 2) {
            int d0 = nbase & 63;
            int p = (s << 5) + (d0 >> 1);
            float c0 = g_cos[p],     s0 = g_sin[p];
            float c1 = g_cos[p + 1], s1 = g_sin[p + 1];
            float e0 = vv[0] * c0 - vv[1] * s0;
            float o0 = vv[0] * s0 + vv[1] * c0;
            float e1 = vv[2] * c1 - vv[3] * s1;
            float o1 = vv[2] * s1 + vv[3] * c1;
            vv[0] = e0; vv[1] = o0; vv[2] = e1; vv[3] = o1;
        }

        float4 res = make_float4(vv[0], vv[1], vv[2], vv[3]);
        if (MODE == 0) {
            *(float4*)&out[(size_t)m * F_DIM + nbase] = res;
        } else {
            int head = nbase >> 6, d = nbase & 63;
            *(float4*)&out[(((size_t)b * NHEAD + head) * S_LEN + s) * HD + d] = res;
        }
    }
}

// ---------------------------------------------------------------------------
// Flash attention: BLOCK_M = BLOCK_N = 64, D = 64, fp32, online softmax.
// grid (S/64, NB), 256 threads, 4x4 score/out micro-tiles per thread.
// ---------------------------------------------------------------------------
__global__ __launch_bounds__(256) void flash_kernel() {
    extern __shared__ float sm[];
    float* QsT = sm;                  // [d][FPAD] (d-major), pre-scaled by 1/8
    float* KsT = sm + 64 * FPAD;      // [d][FPAD]
    float* Vs  = sm + 2 * 64 * FPAD;  // [n][FPAD]
    float* Ps  = sm + 3 * 64 * FPAD;  // [m][FPAD]

    int tid = threadIdx.x;
    int tx = tid & 15, ty = tid >> 4;
    int q0 = blockIdx.x * 64;
    size_t hoff = (size_t)blockIdx.y * S_LEN * HD;
    const float* Qh = g_Q + hoff;
    const float* Kh = g_K + hoff;
    const float* Vh = g_V + hoff;

    int ln = tid & 63;          // row within tile
    int ld = (tid >> 6) * 16;   // d-chunk base

    // Q tile -> smem (transposed, pre-scaled by 1/sqrt(D) = 0.125)
    {
        const float* src = Qh + (size_t)(q0 + ln) * HD + ld;
#pragma unroll
        for (int c = 0; c < 4; c++) {
            float4 v = *(const float4*)(src + c * 4);
            int d = ld + c * 4;
            QsT[(d + 0) * FPAD + ln] = v.x * 0.125f;
            QsT[(d + 1) * FPAD + ln] = v.y * 0.125f;
            QsT[(d + 2) * FPAD + ln] = v.z * 0.125f;
            QsT[(d + 3) * FPAD + ln] = v.w * 0.125f;
        }
    }

    float m_i[4], l_i[4], o[4][4];
#pragma unroll
    for (int i = 0; i < 4; i++) {
        m_i[i] = -3.0e38f;
        l_i[i] = 0.f;
#pragma unroll
        for (int j = 0; j < 4; j++) o[i][j] = 0.f;
    }

    for (int kt = 0; kt < S_LEN / 64; kt++) {
        const float* ksrc = Kh + (size_t)(kt * 64 + ln) * HD + ld;
        const float* vsrc = Vh + (size_t)(kt * 64 + ln) * HD + ld;
#pragma unroll
        for (int c = 0; c < 4; c++) {
            int d = ld + c * 4;
            float4 kv = *(const float4*)(ksrc + c * 4);
            KsT[(d + 0) * FPAD + ln] = kv.x;
            KsT[(d + 1) * FPAD + ln] = kv.y;
            KsT[(d + 2) * FPAD + ln] = kv.z;
            KsT[(d + 3) * FPAD + ln] = kv.w;
            float4 vv = *(const float4*)(vsrc + c * 4);
            *(float4*)&Vs[ln * FPAD + d] = vv;
        }
        __syncthreads();

        // S = (Q/8) K^T
        float sacc[4][4];
#pragma unroll
        for (int i = 0; i < 4; i++)
#pragma unroll
            for (int j = 0; j < 4; j++) sacc[i][j] = 0.f;

#pragma unroll 16
        for (int d = 0; d < 64; d++) {
            float4 qa = *(const float4*)&QsT[d * FPAD + ty * 4];
            float4 kb = *(const float4*)&KsT[d * FPAD + tx * 4];
            float af[4] = {qa.x, qa.y, qa.z, qa.w};
            float bf[4] = {kb.x, kb.y, kb.z, kb.w};
#pragma unroll
            for (int i = 0; i < 4; i++)
#pragma unroll
                for (int j = 0; j < 4; j++)
                    sacc[i][j] = fmaf(af[i], bf[j], sacc[i][j]);
        }

        // online softmax (row groups = 16 lanes sharing ty, same half-warp)
#pragma unroll
        for (int i = 0; i < 4; i++) {
            float rmax = fmaxf(fmaxf(sacc[i][0], sacc[i][1]),
                               fmaxf(sacc[i][2], sacc[i][3]));
#pragma unroll
            for (int off = 8; off >= 1; off >>= 1)
                rmax = fmaxf(rmax, __shfl_xor_sync(0xffffffffu, rmax, off));
            float mnew = fmaxf(m_i[i], rmax);
            float alpha = __expf(m_i[i] - mnew);
            float p0 = __expf(sacc[i][0] - mnew);
            float p1 = __expf(sacc[i][1] - mnew);
            float p2 = __expf(sacc[i][2] - mnew);
            float p3 = __expf(sacc[i][3] - mnew);
            float rsum = p0 + p1 + p2 + p3;
#pragma unroll
            for (int off = 8; off >= 1; off >>= 1)
                rsum += __shfl_xor_sync(0xffffffffu, rsum, off);
            l_i[i] = l_i[i] * alpha + rsum;
            m_i[i] = mnew;
#pragma unroll
            for (int j = 0; j < 4; j++) o[i][j] *= alpha;
            *(float4*)&Ps[(ty * 4 + i) * FPAD + tx * 4] = make_float4(p0, p1, p2, p3);
        }
        __syncthreads();

        // O += P @ V
#pragma unroll 8
        for (int n = 0; n < 64; n++) {
            float4 vb = *(const float4*)&Vs[n * FPAD + tx * 4];
            float bf[4] = {vb.x, vb.y, vb.z, vb.w};
#pragma unroll
            for (int i = 0; i < 4; i++) {
                float p = Ps[(ty * 4 + i) * FPAD + n];
#pragma unroll
                for (int j = 0; j < 4; j++)
                    o[i][j] = fmaf(p, bf[j], o[i][j]);
            }
        }
        __syncthreads();
    }

    // normalize + write to (s, b, f) layout for output projection
    int bb = blockIdx.y >> 3;
    int hh = blockIdx.y & 7;
#pragma unroll
    for (int i = 0; i < 4; i++) {
        int srow = q0 + ty * 4 + i;
        float inv = 1.0f / l_i[i];
        float4 ov = make_float4(o[i][0] * inv, o[i][1] * inv,
                                o[i][2] * inv, o[i][3] * inv);
        *(float4*)&g_Y[((size_t)srow * B_SZ + bb) * F_DIM + hh * HD + tx * 4] = ov;
    }
}

// ---------------------------------------------------------------------------
// launch
// ---------------------------------------------------------------------------
extern "C" void kernel_launch(void* const* d_in, const int* in_sizes, int n_in,
                              void* d_out, int out_size) {
    const float* q  = (const float*)d_in[0];
    const float* k  = (const float*)d_in[1];
    const float* v  = (const float*)d_in[2];
    const float* Wq = (const float*)d_in[3];
    const float* bq = (const float*)d_in[4];
    const float* Wk = (const float*)d_in[5];
    const float* bk = (const float*)d_in[6];
    const float* Wv = (const float*)d_in[7];
    const float* bv = (const float*)d_in[8];
    const float* Wo = (const float*)d_in[9];
    const float* bo = (const float*)d_in[10];
    float* out = (float*)d_out;

    float *pQ, *pK, *pV, *pY;
    cudaGetSymbolAddress((void**)&pQ, g_Q);
    cudaGetSymbolAddress((void**)&pK, g_K);
    cudaGetSymbolAddress((void**)&pV, g_V);
    cudaGetSymbolAddress((void**)&pY, g_Y);

    const int FLASH_SMEM = 4 * 64 * FPAD * sizeof(float);  // 69632 B
    cudaFuncSetAttribute(flash_kernel,
                         cudaFuncAttributeMaxDynamicSharedMemorySize, FLASH_SMEM);

    rope_table_kernel<<<256, 256>>>();

    dim3 pg(F_DIM / 64, M_ROWS / 64);  // (8, 128)
    proj_kernel<2><<<pg, 256>>>(q, Wq, bq, pQ);
    proj_kernel<2><<<pg, 256>>>(k, Wk, bk, pK);
    proj_kernel<1><<<pg, 256>>>(v, Wv, bv, pV);

    flash_kernel<<<dim3(S_LEN / 64, NB), 256, FLASH_SMEM>>>();

    proj_kernel<0><<<pg, 256>>>(pY, Wo, bo, out);
}